// round 3
// baseline (speedup 1.0000x reference)
#include <cuda_runtime.h>
#include <math.h>
#include <stdint.h>

// Problem constants (fixed by the reference)
#define NHEAD 8
#define NLVL 4
#define NPNT 4
#define BB 4
#define NQ 8000
#define CC 256
#define DH 32
#define STOT 19947   // 100*150 + 50*75 + 25*38 + 13*19

// Scratch (static device globals: allocation-free)
static __device__ float g_value[(size_t)BB * STOT * CC];   // [B,S,NH,DH] = [B,S,C]
static __device__ float g_off  [(size_t)BB * NQ * CC];     // [B,Nq,NH*NL*NP*2]
static __device__ float g_attn [(size_t)BB * NQ * 128];    // [B,Nq,NH*16] logits
static __device__ float g_tout [(size_t)BB * NQ * CC];     // [B,Nq,NH,DH]

// ---------------------------------------------------------------------------
// SGEMM: C[m,n] = sum_k A[m,k] * W[n,k] + bias[n]
// A: [M,K] row-major, W: [N,K] row-major ("NT" — both K-contiguous)
// BM=BN=128, BK=16, 256 threads, 8x8 per thread.
// ---------------------------------------------------------------------------
__global__ __launch_bounds__(256) void sgemm_nt_bias(
    const float* __restrict__ A, const float* __restrict__ W,
    const float* __restrict__ bias, float* __restrict__ C,
    int M, int N, int K)
{
    __shared__ float As[16][128];
    __shared__ float Ws[16][128];

    const int tid = threadIdx.x;
    const int m0 = blockIdx.x * 128;
    const int n0 = blockIdx.y * 128;
    const int tr = (tid >> 4) << 3;
    const int tc = (tid & 15) << 3;

    const int lRow = tid >> 2;
    const int lCol = (tid & 3) << 2;

    float acc[8][8];
#pragma unroll
    for (int i = 0; i < 8; i++)
#pragma unroll
        for (int j = 0; j < 8; j++) acc[i][j] = 0.f;

    for (int k0 = 0; k0 < K; k0 += 16) {
#pragma unroll
        for (int hh = 0; hh < 2; hh++) {
            int mr = lRow + hh * 64;
            int m = m0 + mr;
            float4 va = make_float4(0.f, 0.f, 0.f, 0.f);
            if (m < M)
                va = *reinterpret_cast<const float4*>(A + (size_t)m * K + k0 + lCol);
            As[lCol + 0][mr] = va.x;
            As[lCol + 1][mr] = va.y;
            As[lCol + 2][mr] = va.z;
            As[lCol + 3][mr] = va.w;

            int n = n0 + mr;
            float4 vw = *reinterpret_cast<const float4*>(W + (size_t)n * K + k0 + lCol);
            Ws[lCol + 0][mr] = vw.x;
            Ws[lCol + 1][mr] = vw.y;
            Ws[lCol + 2][mr] = vw.z;
            Ws[lCol + 3][mr] = vw.w;
        }
        __syncthreads();

#pragma unroll
        for (int kk = 0; kk < 16; kk++) {
            float ra[8], rw[8];
#pragma unroll
            for (int i = 0; i < 8; i++) ra[i] = As[kk][tr + i];
#pragma unroll
            for (int j = 0; j < 8; j++) rw[j] = Ws[kk][tc + j];
#pragma unroll
            for (int i = 0; i < 8; i++)
#pragma unroll
                for (int j = 0; j < 8; j++)
                    acc[i][j] = fmaf(ra[i], rw[j], acc[i][j]);
        }
        __syncthreads();
    }

    float bv[8];
#pragma unroll
    for (int j = 0; j < 8; j++) bv[j] = bias[n0 + tc + j];

#pragma unroll
    for (int i = 0; i < 8; i++) {
        int m = m0 + tr + i;
        if (m >= M) continue;
        float* crow = C + (size_t)m * N + n0 + tc;
#pragma unroll
        for (int j = 0; j < 8; j++) crow[j] = acc[i][j] + bv[j];
    }
}

// ---------------------------------------------------------------------------
// Fused softmax + bilinear sampling + attention reduce, v2.
// One warp per (b, q, h).
//   lane layout: g = lane>>3  -> point-within-level (0..3)
//                c = lane&7   -> float4 channel group (channels 4c..4c+3)
// Per level (4 total): 3 SHFL broadcasts + 4 predicated LDG.128 + bilinear FMA.
// Final: float4 butterfly reduce over lane groups (offsets 8,16).
// ---------------------------------------------------------------------------
__global__ __launch_bounds__(256) void msda_sampler(
    const float* __restrict__ value,    // [B,S,NH*DH]
    const float* __restrict__ off,      // [B*Nq, 256]
    const float* __restrict__ logits,   // [B*Nq, 128]
    const float* __restrict__ refp,     // [B,Nq,NL,2]
    float* __restrict__ out)            // [B*Nq, NH*DH]
{
    constexpr int LH[NLVL] = {100, 50, 25, 13};
    constexpr int LW[NLVL] = {150, 75, 38, 19};
    constexpr int LS[NLVL] = {0, 15000, 18750, 19700};

    const int gw   = (blockIdx.x << 3) + (threadIdx.x >> 5);
    const int lane = threadIdx.x & 31;
    if (gw >= BB * NQ * NHEAD) return;

    const int h  = gw & 7;
    const int bq = gw >> 3;         // b*Nq + q
    const int b  = bq / NQ;

    const unsigned FULL = 0xffffffffu;

    // --- softmax over the 16 logits of this (b,q,h) ---
    const float* lg = logits + (size_t)bq * 128 + h * 16;
    float myl = (lane < 16) ? lg[lane] : -1e30f;
    float mx = myl;
#pragma unroll
    for (int o = 16; o >= 1; o >>= 1) mx = fmaxf(mx, __shfl_xor_sync(FULL, mx, o));
    float e = (lane < 16) ? expf(myl - mx) : 0.f;
    float s = e;
#pragma unroll
    for (int o = 16; o >= 1; o >>= 1) s += __shfl_xor_sync(FULL, s, o);
    const float aw = e * (1.f / s);     // lane pi (<16) holds weight of point pi

    // --- per-point pixel coords, computed in lanes 0..15 (pi = lane) ---
    float px = 0.f, py = 0.f;
    if (lane < 16) {
        const int l = lane >> 2;
        const float2 o2 = *reinterpret_cast<const float2*>(
            off + (size_t)bq * 256 + h * 32 + lane * 2);
        const float2 r2 = *reinterpret_cast<const float2*>(
            refp + (size_t)bq * (NLVL * 2) + l * 2);
        const float fW = (l == 0) ? 150.f : (l == 1) ? 75.f : (l == 2) ? 38.f : 19.f;
        const float fH = (l == 0) ? 100.f : (l == 1) ? 50.f : (l == 2) ? 25.f : 13.f;
        // match reference: loc = ref + off/norm; pix = loc*size - 0.5
        px = (r2.x + o2.x / fW) * fW - 0.5f;
        py = (r2.y + o2.y / fH) * fH - 0.5f;
    }

    const int g  = lane >> 3;       // point slot within level
    const int c4 = (lane & 7) << 2; // channel offset

    float4 acc = make_float4(0.f, 0.f, 0.f, 0.f);

#pragma unroll
    for (int l = 0; l < NLVL; l++) {
        const int Hd = LH[l], Wd = LW[l];
        const int src = (l << 2) + g;   // source lane holding this point's params
        const float xP  = __shfl_sync(FULL, px, src);
        const float yP  = __shfl_sync(FULL, py, src);
        const float awP = __shfl_sync(FULL, aw, src);

        const float xf = floorf(xP), yf = floorf(yP);
        const float wx1 = xP - xf, wy1 = yP - yf;
        const float wx0 = 1.f - wx1, wy0 = 1.f - wy1;
        const int ix0 = (int)xf, iy0 = (int)yf;
        const int ix1 = ix0 + 1, iy1 = iy0 + 1;

        const bool vx0 = (ix0 >= 0) & (ix0 < Wd);
        const bool vx1 = (ix1 >= 0) & (ix1 < Wd);
        const bool vy0 = (iy0 >= 0) & (iy0 < Hd);
        const bool vy1 = (iy1 >= 0) & (iy1 < Hd);

        const float* vb = value + ((size_t)(b * STOT + LS[l])) * CC + h * DH + c4;

        float4 v00 = make_float4(0.f, 0.f, 0.f, 0.f);
        float4 v10 = v00, v01 = v00, v11 = v00;
        if (vx0 & vy0) v00 = *reinterpret_cast<const float4*>(vb + (size_t)(iy0 * Wd + ix0) * CC);
        if (vx1 & vy0) v10 = *reinterpret_cast<const float4*>(vb + (size_t)(iy0 * Wd + ix1) * CC);
        if (vx0 & vy1) v01 = *reinterpret_cast<const float4*>(vb + (size_t)(iy1 * Wd + ix0) * CC);
        if (vx1 & vy1) v11 = *reinterpret_cast<const float4*>(vb + (size_t)(iy1 * Wd + ix1) * CC);

        const float w00 = wx0 * wy0, w10 = wx1 * wy0;
        const float w01 = wx0 * wy1, w11 = wx1 * wy1;

        acc.x = fmaf(awP, w00 * v00.x + w10 * v10.x + w01 * v01.x + w11 * v11.x, acc.x);
        acc.y = fmaf(awP, w00 * v00.y + w10 * v10.y + w01 * v01.y + w11 * v11.y, acc.y);
        acc.z = fmaf(awP, w00 * v00.z + w10 * v10.z + w01 * v01.z + w11 * v11.z, acc.z);
        acc.w = fmaf(awP, w00 * v00.w + w10 * v10.w + w01 * v01.w + w11 * v11.w, acc.w);
    }

    // --- reduce over the 4 lane groups (same channels at lane offsets 8,16,24) ---
#pragma unroll
    for (int o = 8; o <= 16; o <<= 1) {
        acc.x += __shfl_xor_sync(FULL, acc.x, o);
        acc.y += __shfl_xor_sync(FULL, acc.y, o);
        acc.z += __shfl_xor_sync(FULL, acc.z, o);
        acc.w += __shfl_xor_sync(FULL, acc.w, o);
    }

    if (g == 0)
        *reinterpret_cast<float4*>(out + (size_t)bq * CC + h * DH + c4) = acc;
}

// ---------------------------------------------------------------------------
// kernel_launch
// ---------------------------------------------------------------------------
extern "C" void kernel_launch(void* const* d_in, const int* in_sizes, int n_in,
                              void* d_out, int out_size)
{
    const float* query        = (const float*)d_in[0];
    const float* value_levels = (const float*)d_in[1];
    const float* refp         = (const float*)d_in[2];
    // d_in[3] = spatial_shapes (int32) — compile-time constants, unused
    const float* W_off  = (const float*)d_in[4];
    const float* b_off  = (const float*)d_in[5];
    const float* W_attn = (const float*)d_in[6];
    const float* b_attn = (const float*)d_in[7];
    const float* W_val  = (const float*)d_in[8];
    const float* b_val  = (const float*)d_in[9];
    const float* W_out  = (const float*)d_in[10];
    const float* b_out  = (const float*)d_in[11];
    float* out = (float*)d_out;

    float *gv, *go, *ga, *gt;
    cudaGetSymbolAddress((void**)&gv, g_value);
    cudaGetSymbolAddress((void**)&go, g_off);
    cudaGetSymbolAddress((void**)&ga, g_attn);
    cudaGetSymbolAddress((void**)&gt, g_tout);

    const int Mv = BB * STOT;   // 79788
    const int Mq = BB * NQ;     // 32000

    // 1) value projection
    sgemm_nt_bias<<<dim3((Mv + 127) / 128, 2), 256>>>(value_levels, W_val, b_val, gv, Mv, 256, 256);
    // 2) sampling offsets
    sgemm_nt_bias<<<dim3((Mq + 127) / 128, 2), 256>>>(query, W_off, b_off, go, Mq, 256, 256);
    // 3) attention logits
    sgemm_nt_bias<<<dim3((Mq + 127) / 128, 1), 256>>>(query, W_attn, b_attn, ga, Mq, 128, 256);
    // 4) fused softmax + bilinear sample + reduce  (256000 warps, 8 warps/block)
    msda_sampler<<<(BB * NQ * NHEAD) / 8, 256>>>(gv, go, ga, refp, gt);
    // 5) output projection
    sgemm_nt_bias<<<dim3((Mq + 127) / 128, 2), 256>>>(gt, W_out, b_out, out, Mq, 256, 256);
}

// round 7
// speedup vs baseline: 2.9232x; 2.9232x over previous
#include <cuda_runtime.h>
#include <cuda_bf16.h>
#include <math.h>
#include <stdint.h>

// Problem constants (fixed by the reference)
#define NHEAD 8
#define NLVL 4
#define NPNT 4
#define BB 4
#define NQ 8000
#define CC 256
#define DH 32
#define STOT 19947   // 100*150 + 50*75 + 25*38 + 13*19

// Scratch (static device globals: allocation-free)
static __device__ float g_value[(size_t)BB * STOT * CC];   // [B,S,NH,DH] = [B,S,C]
static __device__ float g_off  [(size_t)BB * NQ * CC];     // [B,Nq,NH*NL*NP*2]
static __device__ float g_attn [(size_t)BB * NQ * 128];    // [B,Nq,NH*16] logits
static __device__ float g_tout [(size_t)BB * NQ * CC];     // [B,Nq,NH,DH]

// ---------------------------------------------------------------------------
// Split-bf16 tensor-core GEMM:  C[m,n] = sum_k A[m,k]*W[n,k] + bias[n]
// fp32 in / fp32 out.  Internally each fp32 -> (hi, lo) bf16 pair; K is
// tripled with diagonal pattern A'=[hi,hi,lo], W'=[hi,lo,hi] so one bf16 GEMM
// computes hiA*hiB + hiA*loB + loA*hiB  (error ~2^-17).
// CTA tile 128x128, 8 warps (warp tile 64x32), BK = 16 fp32 = 48 bf16 slots.
// mma.sync.aligned.m16n8k16.row.col.f32.bf16.bf16.f32
// ---------------------------------------------------------------------------
#define GBM 128
#define GBN 128
#define GBKF 16          // fp32 k per tile
#define GSLOT 48         // bf16 slots per row (3 * GBKF)
#define GSS 56           // padded smem row stride in bf16 (conflict-free)

__device__ __forceinline__ void mma16816(float* d, const uint32_t* a, const uint32_t* b)
{
    asm volatile(
        "mma.sync.aligned.m16n8k16.row.col.f32.bf16.bf16.f32 "
        "{%0,%1,%2,%3}, {%4,%5,%6,%7}, {%8,%9}, {%0,%1,%2,%3};\n"
        : "+f"(d[0]), "+f"(d[1]), "+f"(d[2]), "+f"(d[3])
        : "r"(a[0]), "r"(a[1]), "r"(a[2]), "r"(a[3]), "r"(b[0]), "r"(b[1]));
}

__device__ __forceinline__ void split_pack_A(float4 v, unsigned short* u)
{
    // pattern per fp32 j: [hi, hi, lo]
    const float f[4] = {v.x, v.y, v.z, v.w};
#pragma unroll
    for (int j = 0; j < 4; j++) {
        __nv_bfloat16 h = __float2bfloat16(f[j]);
        __nv_bfloat16 l = __float2bfloat16(f[j] - __bfloat162float(h));
        unsigned short hb = __bfloat16_as_ushort(h);
        unsigned short lb = __bfloat16_as_ushort(l);
        u[3 * j + 0] = hb; u[3 * j + 1] = hb; u[3 * j + 2] = lb;
    }
}

__device__ __forceinline__ void split_pack_B(float4 v, unsigned short* u)
{
    // pattern per fp32 j: [hi, lo, hi]
    const float f[4] = {v.x, v.y, v.z, v.w};
#pragma unroll
    for (int j = 0; j < 4; j++) {
        __nv_bfloat16 h = __float2bfloat16(f[j]);
        __nv_bfloat16 l = __float2bfloat16(f[j] - __bfloat162float(h));
        unsigned short hb = __bfloat16_as_ushort(h);
        unsigned short lb = __bfloat16_as_ushort(l);
        u[3 * j + 0] = hb; u[3 * j + 1] = lb; u[3 * j + 2] = hb;
    }
}

__device__ __forceinline__ void store12(__nv_bfloat16* base, const unsigned short* u)
{
    uint2* dst = reinterpret_cast<uint2*>(base);
    uint2 w0, w1, w2;
    w0.x = (uint32_t)u[0]  | ((uint32_t)u[1]  << 16);
    w0.y = (uint32_t)u[2]  | ((uint32_t)u[3]  << 16);
    w1.x = (uint32_t)u[4]  | ((uint32_t)u[5]  << 16);
    w1.y = (uint32_t)u[6]  | ((uint32_t)u[7]  << 16);
    w2.x = (uint32_t)u[8]  | ((uint32_t)u[9]  << 16);
    w2.y = (uint32_t)u[10] | ((uint32_t)u[11] << 16);
    dst[0] = w0; dst[1] = w1; dst[2] = w2;
}

__global__ __launch_bounds__(256, 2) void gemm_split_bf16(
    const float* __restrict__ A, const float* __restrict__ W,
    const float* __restrict__ bias, float* __restrict__ C,
    int M, int N, int K)
{
    __shared__ __nv_bfloat16 As[GBM * GSS];
    __shared__ __nv_bfloat16 Bs[GBN * GSS];

    const int tid  = threadIdx.x;
    const int lane = tid & 31;
    const int warp = tid >> 5;
    const int warpM = warp & 1;       // 0..1  (64-row groups)
    const int warpN = warp >> 1;      // 0..3  (32-col groups)
    const int m0 = blockIdx.x * GBM;
    const int n0 = blockIdx.y * GBN;

    float acc[4][4][4];
#pragma unroll
    for (int i = 0; i < 4; i++)
#pragma unroll
        for (int j = 0; j < 4; j++)
#pragma unroll
            for (int r = 0; r < 4; r++) acc[i][j][r] = 0.f;

    // loader: 512 float4-chunks per tile per matrix (128 rows x 4 chunks),
    // 256 threads -> 2 chunks each.  chunk: row = c>>2, c4 = c&3.
    const int c0i = tid, c1i = tid + 256;
    const int ar0 = c0i >> 2, ac0 = c0i & 3;
    const int ar1 = c1i >> 2, ac1 = c1i & 3;

    float4 pa0, pa1, pb0, pb1;

    // prefetch tile 0
    {
        pa0 = make_float4(0.f, 0.f, 0.f, 0.f);
        pa1 = pa0;
        if (m0 + ar0 < M) pa0 = *reinterpret_cast<const float4*>(A + (size_t)(m0 + ar0) * K + ac0 * 4);
        if (m0 + ar1 < M) pa1 = *reinterpret_cast<const float4*>(A + (size_t)(m0 + ar1) * K + ac1 * 4);
        pb0 = *reinterpret_cast<const float4*>(W + (size_t)(n0 + ar0) * K + ac0 * 4);
        pb1 = *reinterpret_cast<const float4*>(W + (size_t)(n0 + ar1) * K + ac1 * 4);
    }

    const int nTiles = K / GBKF;
    for (int t = 0; t < nTiles; t++) {
        __syncthreads();
        {
            unsigned short u[12];
            split_pack_A(pa0, u); store12(&As[ar0 * GSS + ac0 * 12], u);
            split_pack_A(pa1, u); store12(&As[ar1 * GSS + ac1 * 12], u);
            split_pack_B(pb0, u); store12(&Bs[ar0 * GSS + ac0 * 12], u);
            split_pack_B(pb1, u); store12(&Bs[ar1 * GSS + ac1 * 12], u);
        }
        __syncthreads();

        if (t + 1 < nTiles) {
            const int k0 = (t + 1) * GBKF;
            pa0 = make_float4(0.f, 0.f, 0.f, 0.f);
            pa1 = pa0;
            if (m0 + ar0 < M) pa0 = *reinterpret_cast<const float4*>(A + (size_t)(m0 + ar0) * K + k0 + ac0 * 4);
            if (m0 + ar1 < M) pa1 = *reinterpret_cast<const float4*>(A + (size_t)(m0 + ar1) * K + k0 + ac1 * 4);
            pb0 = *reinterpret_cast<const float4*>(W + (size_t)(n0 + ar0) * K + k0 + ac0 * 4);
            pb1 = *reinterpret_cast<const float4*>(W + (size_t)(n0 + ar1) * K + k0 + ac1 * 4);
        }

        // compute: 3 k16-steps over the 48 bf16 slots
#pragma unroll
        for (int ks = 0; ks < 3; ks++) {
            uint32_t bfr[4][2];
#pragma unroll
            for (int an = 0; an < 4; an++) {
                const uint32_t* bp = reinterpret_cast<const uint32_t*>(
                    &Bs[(warpN * 32 + an * 8 + (lane >> 2)) * GSS + ks * 16 + (lane & 3) * 2]);
                bfr[an][0] = bp[0];
                bfr[an][1] = bp[4];      // +8 bf16
            }
#pragma unroll
            for (int am = 0; am < 4; am++) {
                const uint32_t* ap = reinterpret_cast<const uint32_t*>(
                    &As[(warpM * 64 + am * 16 + (lane >> 2)) * GSS + ks * 16 + (lane & 3) * 2]);
                uint32_t afr[4];
                afr[0] = ap[0];
                afr[1] = ap[8 * GSS / 2];        // +8 rows
                afr[2] = ap[4];                  // +8 bf16
                afr[3] = ap[8 * GSS / 2 + 4];
#pragma unroll
                for (int an = 0; an < 4; an++)
                    mma16816(acc[am][an], afr, bfr[an]);
            }
        }
    }

    // epilogue: add bias, store fp32
#pragma unroll
    for (int an = 0; an < 4; an++) {
        const int col = n0 + warpN * 32 + an * 8 + (lane & 3) * 2;
        const float b0v = bias[col], b1v = bias[col + 1];
#pragma unroll
        for (int am = 0; am < 4; am++) {
            const int row = m0 + warpM * 64 + am * 16 + (lane >> 2);
            if (row < M) {
                float2* p = reinterpret_cast<float2*>(C + (size_t)row * N + col);
                *p = make_float2(acc[am][an][0] + b0v, acc[am][an][1] + b1v);
            }
            if (row + 8 < M) {
                float2* p = reinterpret_cast<float2*>(C + (size_t)(row + 8) * N + col);
                *p = make_float2(acc[am][an][2] + b0v, acc[am][an][3] + b1v);
            }
        }
    }
}

// ---------------------------------------------------------------------------
// Fused softmax + bilinear sampling + attention reduce (v2, unchanged).
// One warp per (b, q, h); g = lane>>3 point slot, c = lane&7 float4 group.
// ---------------------------------------------------------------------------
__global__ __launch_bounds__(256) void msda_sampler(
    const float* __restrict__ value,    // [B,S,NH*DH]
    const float* __restrict__ off,      // [B*Nq, 256]
    const float* __restrict__ logits,   // [B*Nq, 128]
    const float* __restrict__ refp,     // [B,Nq,NL,2]
    float* __restrict__ out)            // [B*Nq, NH*DH]
{
    constexpr int LH[NLVL] = {100, 50, 25, 13};
    constexpr int LW[NLVL] = {150, 75, 38, 19};
    constexpr int LS[NLVL] = {0, 15000, 18750, 19700};

    const int gw   = (blockIdx.x << 3) + (threadIdx.x >> 5);
    const int lane = threadIdx.x & 31;
    if (gw >= BB * NQ * NHEAD) return;

    const int h  = gw & 7;
    const int bq = gw >> 3;
    const int b  = bq / NQ;

    const unsigned FULL = 0xffffffffu;

    const float* lg = logits + (size_t)bq * 128 + h * 16;
    float myl = (lane < 16) ? lg[lane] : -1e30f;
    float mx = myl;
#pragma unroll
    for (int o = 16; o >= 1; o >>= 1) mx = fmaxf(mx, __shfl_xor_sync(FULL, mx, o));
    float e = (lane < 16) ? expf(myl - mx) : 0.f;
    float s = e;
#pragma unroll
    for (int o = 16; o >= 1; o >>= 1) s += __shfl_xor_sync(FULL, s, o);
    const float aw = e * (1.f / s);

    float px = 0.f, py = 0.f;
    if (lane < 16) {
        const int l = lane >> 2;
        const float2 o2 = *reinterpret_cast<const float2*>(
            off + (size_t)bq * 256 + h * 32 + lane * 2);
        const float2 r2 = *reinterpret_cast<const float2*>(
            refp + (size_t)bq * (NLVL * 2) + l * 2);
        const float fW = (l == 0) ? 150.f : (l == 1) ? 75.f : (l == 2) ? 38.f : 19.f;
        const float fH = (l == 0) ? 100.f : (l == 1) ? 50.f : (l == 2) ? 25.f : 13.f;
        px = (r2.x + o2.x / fW) * fW - 0.5f;
        py = (r2.y + o2.y / fH) * fH - 0.5f;
    }

    const int g  = lane >> 3;
    const int c4 = (lane & 7) << 2;

    float4 acc = make_float4(0.f, 0.f, 0.f, 0.f);

#pragma unroll
    for (int l = 0; l < NLVL; l++) {
        const int Hd = LH[l], Wd = LW[l];
        const int src = (l << 2) + g;
        const float xP  = __shfl_sync(FULL, px, src);
        const float yP  = __shfl_sync(FULL, py, src);
        const float awP = __shfl_sync(FULL, aw, src);

        const float xf = floorf(xP), yf = floorf(yP);
        const float wx1 = xP - xf, wy1 = yP - yf;
        const float wx0 = 1.f - wx1, wy0 = 1.f - wy1;
        const int ix0 = (int)xf, iy0 = (int)yf;
        const int ix1 = ix0 + 1, iy1 = iy0 + 1;

        const bool vx0 = (ix0 >= 0) & (ix0 < Wd);
        const bool vx1 = (ix1 >= 0) & (ix1 < Wd);
        const bool vy0 = (iy0 >= 0) & (iy0 < Hd);
        const bool vy1 = (iy1 >= 0) & (iy1 < Hd);

        const float* vb = value + ((size_t)(b * STOT + LS[l])) * CC + h * DH + c4;

        float4 v00 = make_float4(0.f, 0.f, 0.f, 0.f);
        float4 v10 = v00, v01 = v00, v11 = v00;
        if (vx0 & vy0) v00 = *reinterpret_cast<const float4*>(vb + (size_t)(iy0 * Wd + ix0) * CC);
        if (vx1 & vy0) v10 = *reinterpret_cast<const float4*>(vb + (size_t)(iy0 * Wd + ix1) * CC);
        if (vx0 & vy1) v01 = *reinterpret_cast<const float4*>(vb + (size_t)(iy1 * Wd + ix0) * CC);
        if (vx1 & vy1) v11 = *reinterpret_cast<const float4*>(vb + (size_t)(iy1 * Wd + ix1) * CC);

        const float w00 = wx0 * wy0, w10 = wx1 * wy0;
        const float w01 = wx0 * wy1, w11 = wx1 * wy1;

        acc.x = fmaf(awP, w00 * v00.x + w10 * v10.x + w01 * v01.x + w11 * v11.x, acc.x);
        acc.y = fmaf(awP, w00 * v00.y + w10 * v10.y + w01 * v01.y + w11 * v11.y, acc.y);
        acc.z = fmaf(awP, w00 * v00.z + w10 * v10.z + w01 * v01.z + w11 * v11.z, acc.z);
        acc.w = fmaf(awP, w00 * v00.w + w10 * v10.w + w01 * v01.w + w11 * v11.w, acc.w);
    }

#pragma unroll
    for (int o = 8; o <= 16; o <<= 1) {
        acc.x += __shfl_xor_sync(FULL, acc.x, o);
        acc.y += __shfl_xor_sync(FULL, acc.y, o);
        acc.z += __shfl_xor_sync(FULL, acc.z, o);
        acc.w += __shfl_xor_sync(FULL, acc.w, o);
    }

    if (g == 0)
        *reinterpret_cast<float4*>(out + (size_t)bq * CC + h * DH + c4) = acc;
}

// ---------------------------------------------------------------------------
// kernel_launch
// ---------------------------------------------------------------------------
extern "C" void kernel_launch(void* const* d_in, const int* in_sizes, int n_in,
                              void* d_out, int out_size)
{
    const float* query        = (const float*)d_in[0];
    const float* value_levels = (const float*)d_in[1];
    const float* refp         = (const float*)d_in[2];
    // d_in[3] = spatial_shapes (int32) — compile-time constants, unused
    const float* W_off  = (const float*)d_in[4];
    const float* b_off  = (const float*)d_in[5];
    const float* W_attn = (const float*)d_in[6];
    const float* b_attn = (const float*)d_in[7];
    const float* W_val  = (const float*)d_in[8];
    const float* b_val  = (const float*)d_in[9];
    const float* W_out  = (const float*)d_in[10];
    const float* b_out  = (const float*)d_in[11];
    float* out = (float*)d_out;

    float *gv, *go, *ga, *gt;
    cudaGetSymbolAddress((void**)&gv, g_value);
    cudaGetSymbolAddress((void**)&go, g_off);
    cudaGetSymbolAddress((void**)&ga, g_attn);
    cudaGetSymbolAddress((void**)&gt, g_tout);

    const int Mv = BB * STOT;   // 79788
    const int Mq = BB * NQ;     // 32000

    // 1) value projection
    gemm_split_bf16<<<dim3((Mv + 127) / 128, 2), 256>>>(value_levels, W_val, b_val, gv, Mv, 256, 256);
    // 2) sampling offsets
    gemm_split_bf16<<<dim3((Mq + 127) / 128, 2), 256>>>(query, W_off, b_off, go, Mq, 256, 256);
    // 3) attention logits
    gemm_split_bf16<<<dim3((Mq + 127) / 128, 1), 256>>>(query, W_attn, b_attn, ga, Mq, 128, 256);
    // 4) fused softmax + bilinear sample + reduce
    msda_sampler<<<(BB * NQ * NHEAD) / 8, 256>>>(gv, go, ga, refp, gt);
    // 5) output projection
    gemm_split_bf16<<<dim3((Mq + 127) / 128, 2), 256>>>(gt, W_out, b_out, out, Mq, 256, 256);
}